// round 5
// baseline (speedup 1.0000x reference)
#include <cuda_runtime.h>
#include <cuda_fp16.h>

// LightGCN: final = 0.25 * (I + A^ + A^2 + A^3) emb, A^ = D^-1/2 A D^-1/2
// N = 12000 (8000 users + 4000 items), dim 64, 300k undirected edges.
//
// R5: single persistent fused kernel (build -> init -> 3 gather layers ->
// store+cleanup) with a custom grid barrier. Row-static warp ownership keeps
// the layer-mean accumulator and invd in registers; out written exactly once.
// Fallback to multi-kernel path if one-wave residency can't be guaranteed.

#define NUSERS 8000
#define NITEMS 4000
#define NN     12000
#define DIM    64
#define WPR    375           // bitmap words per row: ceil(12000/32)
#define PAD    128           // ELL row pad (mean deg ~50, P(>128) ~ 1e-20)
#define NTHREADS 256
#define MINBLK   6           // launch_bounds min blocks/SM (regs <= ~40)

// Scratch (device globals: zero-init at load; left clean after every call).
__device__ unsigned g_bitmap[(size_t)NN * WPR];   // 18 MB dedup bitmap
__device__ int      g_nbr[(size_t)NN * PAD];      // 6 MB ELL column indices
__device__ int      g_deg[NN];
__device__ __half   g_y[3][(size_t)NN * DIM];     // per-layer prescaled embeddings
__device__ unsigned g_bar_count;
__device__ unsigned g_bar_gen;
// fallback-path scratch
__device__ int      g_deg2[NN];
__device__ float    g_invd[NN];

// ---------------------------------------------------------------------------
__device__ __forceinline__ void add_edge(int a, int b) {
    unsigned bit = 1u << (b & 31);
    unsigned old = atomicOr(&g_bitmap[(size_t)a * WPR + (b >> 5)], bit);
    if (!(old & bit)) {
        int pos = atomicAdd(&g_deg[a], 1);
        g_nbr[(size_t)a * PAD + pos] = b;
    }
}

// Classic sense-free generation barrier. Safe iff all blocks co-resident
// (guaranteed by host occupancy check).
__device__ __forceinline__ void grid_sync() {
    __syncthreads();
    if (threadIdx.x == 0) {
        __threadfence();
        unsigned gen = *(volatile unsigned*)&g_bar_gen;
        if (atomicAdd(&g_bar_count, 1u) == gridDim.x - 1) {
            g_bar_count = 0;
            __threadfence();
            atomicExch(&g_bar_gen, gen + 1);
        } else {
            while (*(volatile unsigned*)&g_bar_gen == gen) __nanosleep(32);
        }
        __threadfence();
    }
    __syncthreads();
}

// 8-way unrolled neighbor gather: sum of prescaled fp16 rows, fp32 accum.
__device__ __forceinline__ float2 gather_row(const __half2* __restrict__ y,
                                             const int* __restrict__ nb,
                                             int d, int lane) {
    float sx = 0.0f, sy = 0.0f;
    int k = 0;
    for (; k + 8 <= d; k += 8) {
        int4 i0 = *reinterpret_cast<const int4*>(nb + k);
        int4 i1 = *reinterpret_cast<const int4*>(nb + k + 4);
        float2 f0 = __half22float2(__ldg(y + (size_t)i0.x * 32 + lane));
        float2 f1 = __half22float2(__ldg(y + (size_t)i0.y * 32 + lane));
        float2 f2 = __half22float2(__ldg(y + (size_t)i0.z * 32 + lane));
        float2 f3 = __half22float2(__ldg(y + (size_t)i0.w * 32 + lane));
        float2 f4 = __half22float2(__ldg(y + (size_t)i1.x * 32 + lane));
        float2 f5 = __half22float2(__ldg(y + (size_t)i1.y * 32 + lane));
        float2 f6 = __half22float2(__ldg(y + (size_t)i1.z * 32 + lane));
        float2 f7 = __half22float2(__ldg(y + (size_t)i1.w * 32 + lane));
        sx += (f0.x + f1.x) + (f2.x + f3.x) + (f4.x + f5.x) + (f6.x + f7.x);
        sy += (f0.y + f1.y) + (f2.y + f3.y) + (f4.y + f5.y) + (f6.y + f7.y);
    }
    for (; k < d; ++k) {
        int j = __ldg(&nb[k]);
        float2 f = __half22float2(__ldg(y + (size_t)j * 32 + lane));
        sx += f.x;
        sy += f.y;
    }
    return make_float2(sx, sy);
}

// ---------------------------------------------------------------------------
__global__ void __launch_bounds__(NTHREADS, MINBLK)
lightgcn_fused(const int* __restrict__ ei, int E,
               const float* __restrict__ ue, const float* __restrict__ ie,
               float* __restrict__ out) {
    const int tid    = blockIdx.x * NTHREADS + threadIdx.x;
    const int nwarps = gridDim.x * (NTHREADS / 32);
    const int lane   = threadIdx.x & 31;
    const int gw     = tid >> 5;

    // ---- phase 0: build adjacency (dedup via bitmap, append to ELL) ----
    for (int e = tid; e < E; e += gridDim.x * NTHREADS) {
        int u = ei[e];
        int v = ei[E + e];
        add_edge(u, v);
        add_edge(v, u);
    }
    grid_sync();

    // Owned rows (host guarantees nwarps >= 6000 so <= 2 rows/warp).
    const int r0 = gw;                    // always < NN (nwarps < NN)
    const int r1 = gw + nwarps;
    const bool has1 = (r1 < NN);

    // ---- phase 1: init. acc = 0.25*emb (reg); y0 = half(emb * d^-1/2) ----
    float ax0, ay0, ax1 = 0.f, ay1 = 0.f;
    float invd0, invd1 = 0.f;
    int   d0, d1 = 0;
    {
        d0 = g_deg[r0];
        if (lane == 0) g_deg[r0] = 0;               // clean for next call
        invd0 = rsqrtf((float)(d0 < 1 ? 1 : d0));
        const float* src = (r0 < NUSERS) ? ue + (size_t)r0 * DIM
                                         : ie + (size_t)(r0 - NUSERS) * DIM;
        float2 e = *reinterpret_cast<const float2*>(src + (lane << 1));
        ax0 = 0.25f * e.x; ay0 = 0.25f * e.y;
        reinterpret_cast<__half2*>(g_y[0])[(size_t)r0 * 32 + lane] =
            __floats2half2_rn(e.x * invd0, e.y * invd0);
    }
    if (has1) {
        d1 = g_deg[r1];
        if (lane == 0) g_deg[r1] = 0;
        invd1 = rsqrtf((float)(d1 < 1 ? 1 : d1));
        const float* src = (r1 < NUSERS) ? ue + (size_t)r1 * DIM
                                         : ie + (size_t)(r1 - NUSERS) * DIM;
        float2 e = *reinterpret_cast<const float2*>(src + (lane << 1));
        ax1 = 0.25f * e.x; ay1 = 0.25f * e.y;
        reinterpret_cast<__half2*>(g_y[0])[(size_t)r1 * 32 + lane] =
            __floats2half2_rn(e.x * invd1, e.y * invd1);
    }
    grid_sync();

    const int* __restrict__ nb0 = g_nbr + (size_t)r0 * PAD;
    const int* __restrict__ nb1 = g_nbr + (size_t)r1 * PAD;

    // ---- phases 2..4: three propagation layers ----
    #pragma unroll
    for (int L = 0; L < 3; ++L) {
        const __half2* ysrc = reinterpret_cast<const __half2*>(g_y[L]);
        {
            float2 s = gather_row(ysrc, nb0, d0, lane);
            ax0 += 0.25f * invd0 * s.x;
            ay0 += 0.25f * invd0 * s.y;
            if (L < 2) {
                float q = invd0 * invd0;
                reinterpret_cast<__half2*>(g_y[L + 1])[(size_t)r0 * 32 + lane] =
                    __floats2half2_rn(s.x * q, s.y * q);
            }
        }
        if (has1) {
            float2 s = gather_row(ysrc, nb1, d1, lane);
            ax1 += 0.25f * invd1 * s.x;
            ay1 += 0.25f * invd1 * s.y;
            if (L < 2) {
                float q = invd1 * invd1;
                reinterpret_cast<__half2*>(g_y[L + 1])[(size_t)r1 * 32 + lane] =
                    __floats2half2_rn(s.x * q, s.y * q);
            }
        }
        if (L < 2) grid_sync();
    }

    // ---- final store + bitmap cleanup (clear only touched words) ----
    *reinterpret_cast<float2*>(out + (size_t)r0 * DIM + (lane << 1)) =
        make_float2(ax0, ay0);
    for (int k = lane; k < d0; k += 32)
        g_bitmap[(size_t)r0 * WPR + (nb0[k] >> 5)] = 0u;
    if (has1) {
        *reinterpret_cast<float2*>(out + (size_t)r1 * DIM + (lane << 1)) =
            make_float2(ax1, ay1);
        for (int k = lane; k < d1; k += 32)
            g_bitmap[(size_t)r1 * WPR + (nb1[k] >> 5)] = 0u;
    }
}

// ===========================================================================
// Fallback path (R4 proven kernels) — used only if one-wave residency of the
// fused kernel cannot be guaranteed.
// ===========================================================================
__global__ void build_kernel(const int* __restrict__ ei, int E) {
    int e = blockIdx.x * blockDim.x + threadIdx.x;
    if (e >= E) return;
    int u = ei[e];
    int v = ei[E + e];
    add_edge(u, v);
    add_edge(v, u);
}

__global__ void invd_kernel() {
    int n = blockIdx.x * blockDim.x + threadIdx.x;
    if (n < NN) {
        int d = g_deg[n];
        g_deg2[n] = d;
        g_deg[n]  = 0;
        g_invd[n] = rsqrtf((float)(d < 1 ? 1 : d));
    }
}

__global__ void init_kernel(const float* __restrict__ ue,
                            const float* __restrict__ ie,
                            float* __restrict__ out) {
    int i = blockIdx.x * blockDim.x + threadIdx.x;
    if (i >= NN * DIM / 4) return;
    int n = i >> 4;
    float4 e = (n < NUSERS)
        ? reinterpret_cast<const float4*>(ue)[i]
        : reinterpret_cast<const float4*>(ie)[i - NUSERS * (DIM / 4)];
    reinterpret_cast<float4*>(out)[i] =
        make_float4(0.25f * e.x, 0.25f * e.y, 0.25f * e.z, 0.25f * e.w);
    float id = g_invd[n];
    __half2* yp = reinterpret_cast<__half2*>(g_y[0]) + (size_t)i * 2;
    yp[0] = __floats2half2_rn(e.x * id, e.y * id);
    yp[1] = __floats2half2_rn(e.z * id, e.w * id);
}

__global__ void cleanup_kernel() {
    int t = blockIdx.x * blockDim.x + threadIdx.x;
    if (t >= NN * PAD) return;
    int row = t >> 7;
    int k   = t & (PAD - 1);
    if (k < g_deg2[row])
        g_bitmap[(size_t)row * WPR + (g_nbr[t] >> 5)] = 0u;
}

template <int SRC, int DST, bool LAST>
__global__ void __launch_bounds__(256)
spmm_kernel(float* __restrict__ out) {
    int gw   = (blockIdx.x * blockDim.x + threadIdx.x) >> 5;
    int lane = threadIdx.x & 31;
    if (gw >= NN) return;
    const __half2* y  = reinterpret_cast<const __half2*>(g_y[SRC]);
    const int*     nb = g_nbr + (size_t)gw * PAD;
    int d = g_deg2[gw];
    float2 s = gather_row(y, nb, d, lane);
    float id = g_invd[gw];
    if (!LAST) {
        float q = id * id;
        reinterpret_cast<__half2*>(g_y[DST])[(size_t)gw * 32 + lane] =
            __floats2half2_rn(s.x * q, s.y * q);
    }
    float* op = out + (size_t)gw * DIM + (lane << 1);
    float2 o = *reinterpret_cast<float2*>(op);
    o.x += 0.25f * id * s.x;
    o.y += 0.25f * id * s.y;
    *reinterpret_cast<float2*>(op) = o;
}

// ---------------------------------------------------------------------------
extern "C" void kernel_launch(void* const* d_in, const int* in_sizes, int n_in,
                              void* d_out, int out_size) {
    const int*   edge = (const int*)d_in[0];   // (2, E) int32
    const float* ue   = (const float*)d_in[1]; // (8000, 64) f32
    const float* ie   = (const float*)d_in[2]; // (4000, 64) f32
    float*       out  = (float*)d_out;         // (12000, 64) f32

    int E = in_sizes[0] / 2;

    int occ = 0, sms = 0;
    cudaOccupancyMaxActiveBlocksPerMultiprocessor(&occ, lightgcn_fused,
                                                  NTHREADS, 0);
    cudaDeviceGetAttribute(&sms, cudaDevAttrMultiProcessorCount, 0);
    int blocks = occ * sms;

    if (blocks * (NTHREADS / 32) >= 6000) {       // <= 2 rows/warp guaranteed
        lightgcn_fused<<<blocks, NTHREADS>>>(edge, E, ue, ie, out);
    } else {
        build_kernel<<<(E + 255) / 256, 256>>>(edge, E);
        invd_kernel<<<(NN + 255) / 256, 256>>>();
        init_kernel<<<(NN * DIM / 4 + 255) / 256, 256>>>(ue, ie, out);
        const int SPMM_BLOCKS = (NN * 32 + 255) / 256;
        spmm_kernel<0, 1, false><<<SPMM_BLOCKS, 256>>>(out);
        spmm_kernel<1, 2, false><<<SPMM_BLOCKS, 256>>>(out);
        spmm_kernel<2, 0, true ><<<SPMM_BLOCKS, 256>>>(out);
        cleanup_kernel<<<(NN * PAD + 255) / 256, 256>>>();
    }
}

// round 6
// speedup vs baseline: 1.0395x; 1.0395x over previous
#include <cuda_runtime.h>
#include <cuda_fp16.h>

// LightGCN: final = 0.25 * (I + A^ + A^2 + A^3) emb, A^ = D^-1/2 A D^-1/2
// N = 12000 (8000 users + 4000 items), dim 64, 300k undirected edges.
//
// R6: vectorized gather — lane (g,c)=(l>>3,l&7): group g handles neighbor k+g,
// lane loads uint4 (8 halves) of that row. One LDG.128 = 4 neighbor rows.
// Remainders read a permanent zero row (row NN). shfl reduce across groups.
// Last spmm folds bitmap cleanup. Persistent-kernel path removed (regressed).

#define NUSERS 8000
#define NITEMS 4000
#define NN     12000
#define DIM    64
#define WPR    375           // bitmap words per row: ceil(12000/32)
#define PAD    128           // ELL row pad (mean deg ~50, P(>128) ~ 1e-20)

// Scratch (device globals: zero-init at load; left clean after every call).
__device__ unsigned g_bitmap[(size_t)NN * WPR];       // 18 MB dedup bitmap
__device__ int      g_nbr[(size_t)NN * PAD];          // 6 MB ELL column indices
__device__ int      g_deg[NN];                        // build counter (reset each call)
__device__ int      g_deg2[NN];                       // snapshot for spmm
__device__ float    g_invd[NN];
__device__ __half   g_y[3][(size_t)(NN + 1) * DIM];   // +1: row NN is permanent zeros

// ---------------------------------------------------------------------------
// Dedup via bitmap atomicOr (old value elects exactly one winner per distinct
// directed edge); winner appends to ELL. Self-loops counted once (matches ref).
__device__ __forceinline__ void add_edge(int a, int b) {
    unsigned bit = 1u << (b & 31);
    unsigned old = atomicOr(&g_bitmap[(size_t)a * WPR + (b >> 5)], bit);
    if (!(old & bit)) {
        int pos = atomicAdd(&g_deg[a], 1);
        g_nbr[(size_t)a * PAD + pos] = b;
    }
}

__global__ void build_kernel(const int* __restrict__ ei, int E) {
    int e = blockIdx.x * blockDim.x + threadIdx.x;
    if (e >= E) return;
    int u = ei[e];
    int v = ei[E + e];
    add_edge(u, v);
    add_edge(v, u);
}

// ---------------------------------------------------------------------------
__global__ void invd_kernel() {
    int n = blockIdx.x * blockDim.x + threadIdx.x;
    if (n < NN) {
        int d = g_deg[n];
        g_deg2[n] = d;
        g_deg[n]  = 0;                               // clean for next call
        g_invd[n] = rsqrtf((float)(d < 1 ? 1 : d));
    }
}

// ---------------------------------------------------------------------------
// out = 0.25 * emb (layer-0 term of the mean); y0 = half(emb * d^-1/2).
__global__ void init_kernel(const float* __restrict__ ue,
                            const float* __restrict__ ie,
                            float* __restrict__ out) {
    int i = blockIdx.x * blockDim.x + threadIdx.x;   // float4 index
    if (i >= NN * DIM / 4) return;
    int n = i >> 4;                                  // 16 float4 per row
    float4 e = (n < NUSERS)
        ? reinterpret_cast<const float4*>(ue)[i]
        : reinterpret_cast<const float4*>(ie)[i - NUSERS * (DIM / 4)];
    reinterpret_cast<float4*>(out)[i] =
        make_float4(0.25f * e.x, 0.25f * e.y, 0.25f * e.z, 0.25f * e.w);
    float id = g_invd[n];
    __half2* yp = reinterpret_cast<__half2*>(g_y[0]) + (size_t)i * 2;
    yp[0] = __floats2half2_rn(e.x * id, e.y * id);
    yp[1] = __floats2half2_rn(e.z * id, e.w * id);
}

// ---------------------------------------------------------------------------
__device__ __forceinline__ void acc8(float acc[8], uint4 v) {
    float2 f0 = __half22float2(*reinterpret_cast<__half2*>(&v.x));
    float2 f1 = __half22float2(*reinterpret_cast<__half2*>(&v.y));
    float2 f2 = __half22float2(*reinterpret_cast<__half2*>(&v.z));
    float2 f3 = __half22float2(*reinterpret_cast<__half2*>(&v.w));
    acc[0] += f0.x; acc[1] += f0.y; acc[2] += f1.x; acc[3] += f1.y;
    acc[4] += f2.x; acc[5] += f2.y; acc[6] += f3.x; acc[7] += f3.y;
}

// One warp per row. Lane l: group g=l>>3 serves neighbor k+g, chunk c=l&7 owns
// dims [8c, 8c+8). Each LDG.128 gathers 4 neighbor rows (512B/warp). Padded
// slots read zero row NN. After the loop, shfl_xor(8,16) reduces the 4 groups.
//   y_next = half(d^-1 * s)   (skipped on last layer)
//   out   += 0.25 * d^-1/2 * s
//   LAST: clear this row's bitmap words (fold cleanup into the pass).
template <int SRC, int DST, bool LAST>
__global__ void __launch_bounds__(256)
spmm_kernel(float* __restrict__ out) {
    int gw   = (blockIdx.x * blockDim.x + threadIdx.x) >> 5;
    int lane = threadIdx.x & 31;
    if (gw >= NN) return;
    const int g = lane >> 3;
    const int c = lane & 7;

    const uint4* __restrict__ y  = reinterpret_cast<const uint4*>(g_y[SRC]);
    const int*   __restrict__ nb = g_nbr + (size_t)gw * PAD;
    const int d = g_deg2[gw];

    float acc[8] = {0.f, 0.f, 0.f, 0.f, 0.f, 0.f, 0.f, 0.f};

    for (int k = 0; k < d; k += 8) {
        int k0 = k + g;
        int k1 = k + 4 + g;
        int j0 = (k0 < d) ? __ldg(nb + k0) : NN;
        int j1 = (k1 < d) ? __ldg(nb + k1) : NN;
        uint4 v0 = __ldg(y + (size_t)j0 * 8 + c);
        uint4 v1 = __ldg(y + (size_t)j1 * 8 + c);
        acc8(acc, v0);
        acc8(acc, v1);
    }

    // Reduce the 4 neighbor-groups (lanes 8 and 16 apart share the same c).
    #pragma unroll
    for (int i = 0; i < 8; ++i) {
        acc[i] += __shfl_xor_sync(0xffffffffu, acc[i], 8);
        acc[i] += __shfl_xor_sync(0xffffffffu, acc[i], 16);
    }

    float id = g_invd[gw];

    if (!LAST && g == 0) {
        float q = id * id;
        __half2 p0 = __floats2half2_rn(acc[0] * q, acc[1] * q);
        __half2 p1 = __floats2half2_rn(acc[2] * q, acc[3] * q);
        __half2 p2 = __floats2half2_rn(acc[4] * q, acc[5] * q);
        __half2 p3 = __floats2half2_rn(acc[6] * q, acc[7] * q);
        uint4 o;
        o.x = *reinterpret_cast<unsigned*>(&p0);
        o.y = *reinterpret_cast<unsigned*>(&p1);
        o.z = *reinterpret_cast<unsigned*>(&p2);
        o.w = *reinterpret_cast<unsigned*>(&p3);
        reinterpret_cast<uint4*>(g_y[DST])[(size_t)gw * 8 + c] = o;
    }

    if (g == 1) {  // a different group does the out RMW (spread store work)
        float s = 0.25f * id;
        float4* op = reinterpret_cast<float4*>(out + (size_t)gw * DIM + c * 8);
        float4 t0 = op[0], t1 = op[1];
        t0.x += s * acc[0]; t0.y += s * acc[1];
        t0.z += s * acc[2]; t0.w += s * acc[3];
        t1.x += s * acc[4]; t1.y += s * acc[5];
        t1.z += s * acc[6]; t1.w += s * acc[7];
        op[0] = t0; op[1] = t1;
    }

    if (LAST) {  // fold bitmap cleanup: clear exactly this row's touched words
        for (int k = lane; k < d; k += 32)
            g_bitmap[(size_t)gw * WPR + (nb[k] >> 5)] = 0u;
    }
}

// ---------------------------------------------------------------------------
extern "C" void kernel_launch(void* const* d_in, const int* in_sizes, int n_in,
                              void* d_out, int out_size) {
    const int*   edge = (const int*)d_in[0];   // (2, E) int32
    const float* ue   = (const float*)d_in[1]; // (8000, 64) f32
    const float* ie   = (const float*)d_in[2]; // (4000, 64) f32
    float*       out  = (float*)d_out;         // (12000, 64) f32

    int E = in_sizes[0] / 2;

    build_kernel<<<(E + 255) / 256, 256>>>(edge, E);
    invd_kernel<<<(NN + 255) / 256, 256>>>();
    init_kernel<<<(NN * DIM / 4 + 255) / 256, 256>>>(ue, ie, out);

    const int SPMM_BLOCKS = (NN * 32 + 255) / 256;  // one warp per row
    spmm_kernel<0, 1, false><<<SPMM_BLOCKS, 256>>>(out);
    spmm_kernel<1, 2, false><<<SPMM_BLOCKS, 256>>>(out);
    spmm_kernel<2, 0, true ><<<SPMM_BLOCKS, 256>>>(out);
}

// round 7
// speedup vs baseline: 1.0678x; 1.0272x over previous
#include <cuda_runtime.h>
#include <cuda_fp16.h>

// LightGCN: final = 0.25 * (I + A^ + A^2 + A^3) emb, A^ = D^-1/2 A D^-1/2
// N = 12000 (8000 users + 4000 items), dim 64, 300k undirected edges.
//
// R7: per-chunk register-resident indices distributed via shfl (gathers are the
// only var-lat ops in the hot loop), 42-reg budget for deeper MLP, one-wave
// grid-stride spmm (no wave quantization), invd folded into init.

#define NUSERS 8000
#define NITEMS 4000
#define NN     12000
#define DIM    64
#define WPR    375           // bitmap words per row: ceil(12000/32)
#define PAD    128           // ELL row pad (mean deg ~50, P(>128) ~ 1e-20)
#define SPMM_TPB 256
#define SPMM_BPS 6           // blocks/SM -> <=42 regs, 48 warps/SM

// Scratch (device globals: zero-init at load; left clean after every call).
__device__ unsigned g_bitmap[(size_t)NN * WPR];       // 18 MB dedup bitmap
__device__ int      g_nbr[(size_t)NN * PAD];          // 6 MB ELL column indices
__device__ int      g_deg[NN];                        // build counter (reset each call)
__device__ int      g_deg2[NN];                       // snapshot for spmm
__device__ float    g_invd[NN];
__device__ __half   g_y[3][(size_t)(NN + 1) * DIM];   // +1: row NN is permanent zeros

// ---------------------------------------------------------------------------
// Dedup via bitmap atomicOr (old value elects exactly one winner per distinct
// directed edge); winner appends to ELL. Self-loops counted once (matches ref).
__device__ __forceinline__ void add_edge(int a, int b) {
    unsigned bit = 1u << (b & 31);
    unsigned old = atomicOr(&g_bitmap[(size_t)a * WPR + (b >> 5)], bit);
    if (!(old & bit)) {
        int pos = atomicAdd(&g_deg[a], 1);
        g_nbr[(size_t)a * PAD + pos] = b;
    }
}

__global__ void build_kernel(const int* __restrict__ ei, int E) {
    int e = blockIdx.x * blockDim.x + threadIdx.x;
    if (e >= E) return;
    int u = ei[e];
    int v = ei[E + e];
    add_edge(u, v);
    add_edge(v, u);
}

// ---------------------------------------------------------------------------
// out = 0.25 * emb; y0 = half(emb * d^-1/2). invd computed inline (redundantly
// per 16 threads of a row — cheap); one thread per row snapshots & resets deg.
__global__ void init_kernel(const float* __restrict__ ue,
                            const float* __restrict__ ie,
                            float* __restrict__ out) {
    int i = blockIdx.x * blockDim.x + threadIdx.x;   // float4 index
    if (i >= NN * DIM / 4) return;
    int n = i >> 4;                                  // 16 float4 per row
    int d = g_deg[n];
    float id = rsqrtf((float)(d < 1 ? 1 : d));
    if ((i & 15) == 0) {
        g_deg2[n] = d;
        g_deg[n]  = 0;                               // clean for next call
        g_invd[n] = id;
    }
    float4 e = (n < NUSERS)
        ? reinterpret_cast<const float4*>(ue)[i]
        : reinterpret_cast<const float4*>(ie)[i - NUSERS * (DIM / 4)];
    reinterpret_cast<float4*>(out)[i] =
        make_float4(0.25f * e.x, 0.25f * e.y, 0.25f * e.z, 0.25f * e.w);
    __half2* yp = reinterpret_cast<__half2*>(g_y[0]) + (size_t)i * 2;
    yp[0] = __floats2half2_rn(e.x * id, e.y * id);
    yp[1] = __floats2half2_rn(e.z * id, e.w * id);
}

// ---------------------------------------------------------------------------
__device__ __forceinline__ void acc8(float acc[8], uint4 v) {
    float2 f0 = __half22float2(*reinterpret_cast<__half2*>(&v.x));
    float2 f1 = __half22float2(*reinterpret_cast<__half2*>(&v.y));
    float2 f2 = __half22float2(*reinterpret_cast<__half2*>(&v.z));
    float2 f3 = __half22float2(*reinterpret_cast<__half2*>(&v.w));
    acc[0] += f0.x; acc[1] += f0.y; acc[2] += f1.x; acc[3] += f1.y;
    acc[4] += f2.x; acc[5] += f2.y; acc[6] += f3.x; acc[7] += f3.y;
}

// One warp per row (grid-strided). Lane l: group g=l>>3 serves neighbor 4i+g
// of the current 32-neighbor chunk; chunk c=l&7 owns dims [8c,8c+8).
// Per chunk: ONE coalesced index load (padded slots -> zero row NN), then 8
// fully-unrolled shfl+LDG.128 pairs — gathers are the only var-lat ops.
template <int SRC, int DST, bool LAST>
__global__ void __launch_bounds__(SPMM_TPB, SPMM_BPS)
spmm_kernel(float* __restrict__ out) {
    const int lane   = threadIdx.x & 31;
    const int g      = lane >> 3;
    const int c      = lane & 7;
    const int nwarps = gridDim.x * (SPMM_TPB / 32);
    const uint4* __restrict__ y = reinterpret_cast<const uint4*>(g_y[SRC]);

    for (int row = (blockIdx.x * SPMM_TPB + threadIdx.x) >> 5; row < NN;
         row += nwarps) {
        const int* __restrict__ nb = g_nbr + (size_t)row * PAD;
        const int d = g_deg2[row];

        float acc[8] = {0.f, 0.f, 0.f, 0.f, 0.f, 0.f, 0.f, 0.f};

        for (int base = 0; base < d; base += 32) {
            int slot = base + lane;
            int idx  = (slot < d) ? __ldg(nb + slot) : NN;  // one coalesced load
            #pragma unroll
            for (int i = 0; i < 8; ++i) {
                int j = __shfl_sync(0xffffffffu, idx, i * 4 + g);
                uint4 v = __ldg(y + (size_t)j * 8 + c);
                acc8(acc, v);
            }
        }

        // Reduce the 4 neighbor-groups (lanes 8 and 16 apart share the same c).
        #pragma unroll
        for (int i = 0; i < 8; ++i) {
            acc[i] += __shfl_xor_sync(0xffffffffu, acc[i], 8);
            acc[i] += __shfl_xor_sync(0xffffffffu, acc[i], 16);
        }

        float id = g_invd[row];

        if (!LAST && g == 0) {
            float q = id * id;
            __half2 p0 = __floats2half2_rn(acc[0] * q, acc[1] * q);
            __half2 p1 = __floats2half2_rn(acc[2] * q, acc[3] * q);
            __half2 p2 = __floats2half2_rn(acc[4] * q, acc[5] * q);
            __half2 p3 = __floats2half2_rn(acc[6] * q, acc[7] * q);
            uint4 o;
            o.x = *reinterpret_cast<unsigned*>(&p0);
            o.y = *reinterpret_cast<unsigned*>(&p1);
            o.z = *reinterpret_cast<unsigned*>(&p2);
            o.w = *reinterpret_cast<unsigned*>(&p3);
            reinterpret_cast<uint4*>(g_y[DST])[(size_t)row * 8 + c] = o;
        }

        if (g == 1) {  // different group handles the out RMW
            float s = 0.25f * id;
            float4* op = reinterpret_cast<float4*>(out + (size_t)row * DIM + c * 8);
            float4 t0 = op[0], t1 = op[1];
            t0.x += s * acc[0]; t0.y += s * acc[1];
            t0.z += s * acc[2]; t0.w += s * acc[3];
            t1.x += s * acc[4]; t1.y += s * acc[5];
            t1.z += s * acc[6]; t1.w += s * acc[7];
            op[0] = t0; op[1] = t1;
        }

        if (LAST) {  // fold bitmap cleanup: clear exactly this row's words
            for (int k = lane; k < d; k += 32)
                g_bitmap[(size_t)row * WPR + (nb[k] >> 5)] = 0u;
        }
    }
}

// ---------------------------------------------------------------------------
extern "C" void kernel_launch(void* const* d_in, const int* in_sizes, int n_in,
                              void* d_out, int out_size) {
    const int*   edge = (const int*)d_in[0];   // (2, E) int32
    const float* ue   = (const float*)d_in[1]; // (8000, 64) f32
    const float* ie   = (const float*)d_in[2]; // (4000, 64) f32
    float*       out  = (float*)d_out;         // (12000, 64) f32

    int E = in_sizes[0] / 2;

    build_kernel<<<(E + 255) / 256, 256>>>(edge, E);
    init_kernel<<<(NN * DIM / 4 + 255) / 256, 256>>>(ue, ie, out);

    int sms = 148;
    cudaDeviceGetAttribute(&sms, cudaDevAttrMultiProcessorCount, 0);
    const int SPMM_BLOCKS = sms * SPMM_BPS;          // exactly one wave

    spmm_kernel<0, 1, false><<<SPMM_BLOCKS, SPMM_TPB>>>(out);
    spmm_kernel<1, 2, false><<<SPMM_BLOCKS, SPMM_TPB>>>(out);
    spmm_kernel<2, 0, true ><<<SPMM_BLOCKS, SPMM_TPB>>>(out);
}

// round 9
// speedup vs baseline: 1.1462x; 1.0734x over previous
#include <cuda_runtime.h>
#include <cuda_fp16.h>

// LightGCN: final = 0.25 * (I + A^ + A^2 + A^3) emb, A^ = D^-1/2 A D^-1/2
// N = 12000 (8000 users + 4000 items), dim 64, 300k undirected edges.
//
// R8: R6 gather structure (direct broadcast index loads — shfl variant
// regressed) + TWO rows interleaved per warp (w, w+6000): 16 outstanding
// gathers/warp instead of 8. Epilogue spread across the 4 lane-groups.

#define NUSERS 8000
#define NITEMS 4000
#define NN     12000
#define HALFN  6000
#define DIM    64
#define WPR    375           // bitmap words per row: ceil(12000/32)
#define PAD    128           // ELL row pad (mean deg ~50, P(>128) ~ 1e-20)

// Scratch (device globals: zero-init at load; left clean after every call).
__device__ unsigned g_bitmap[(size_t)NN * WPR];       // 18 MB dedup bitmap
__device__ int      g_nbr[(size_t)NN * PAD];          // 6 MB ELL column indices
__device__ int      g_deg[NN];                        // build counter (reset each call)
__device__ int      g_deg2[NN];                       // snapshot for spmm
__device__ float    g_invd[NN];
__device__ __half   g_y[3][(size_t)(NN + 1) * DIM];   // +1: row NN is permanent zeros

// ---------------------------------------------------------------------------
// Dedup via bitmap atomicOr (old value elects exactly one winner per distinct
// directed edge); winner appends to ELL. Self-loops counted once (matches ref).
__device__ __forceinline__ void add_edge(int a, int b) {
    unsigned bit = 1u << (b & 31);
    unsigned old = atomicOr(&g_bitmap[(size_t)a * WPR + (b >> 5)], bit);
    if (!(old & bit)) {
        int pos = atomicAdd(&g_deg[a], 1);
        g_nbr[(size_t)a * PAD + pos] = b;
    }
}

__global__ void build_kernel(const int* __restrict__ ei, int E) {
    int e = blockIdx.x * blockDim.x + threadIdx.x;
    if (e >= E) return;
    int u = ei[e];
    int v = ei[E + e];
    add_edge(u, v);
    add_edge(v, u);
}

// ---------------------------------------------------------------------------
// out = 0.25 * emb; y0 = half(emb * d^-1/2). invd inline; one thread per row
// snapshots & resets deg.
__global__ void init_kernel(const float* __restrict__ ue,
                            const float* __restrict__ ie,
                            float* __restrict__ out) {
    int i = blockIdx.x * blockDim.x + threadIdx.x;   // float4 index
    if (i >= NN * DIM / 4) return;
    int n = i >> 4;                                  // 16 float4 per row
    int d = g_deg[n];
    float id = rsqrtf((float)(d < 1 ? 1 : d));
    if ((i & 15) == 0) {
        g_deg2[n] = d;
        g_deg[n]  = 0;                               // clean for next call
        g_invd[n] = id;
    }
    float4 e = (n < NUSERS)
        ? reinterpret_cast<const float4*>(ue)[i]
        : reinterpret_cast<const float4*>(ie)[i - NUSERS * (DIM / 4)];
    reinterpret_cast<float4*>(out)[i] =
        make_float4(0.25f * e.x, 0.25f * e.y, 0.25f * e.z, 0.25f * e.w);
    __half2* yp = reinterpret_cast<__half2*>(g_y[0]) + (size_t)i * 2;
    yp[0] = __floats2half2_rn(e.x * id, e.y * id);
    yp[1] = __floats2half2_rn(e.z * id, e.w * id);
}

// ---------------------------------------------------------------------------
__device__ __forceinline__ void acc8(float acc[8], uint4 v) {
    float2 f0 = __half22float2(*reinterpret_cast<__half2*>(&v.x));
    float2 f1 = __half22float2(*reinterpret_cast<__half2*>(&v.y));
    float2 f2 = __half22float2(*reinterpret_cast<__half2*>(&v.z));
    float2 f3 = __half22float2(*reinterpret_cast<__half2*>(&v.w));
    acc[0] += f0.x; acc[1] += f0.y; acc[2] += f1.x; acc[3] += f1.y;
    acc[4] += f2.x; acc[5] += f2.y; acc[6] += f3.x; acc[7] += f3.y;
}

__device__ __forceinline__ void reduce_groups(float acc[8]) {
    #pragma unroll
    for (int i = 0; i < 8; ++i) {
        acc[i] += __shfl_xor_sync(0xffffffffu, acc[i], 8);
        acc[i] += __shfl_xor_sync(0xffffffffu, acc[i], 16);
    }
}

__device__ __forceinline__ void store_ynext(__half* dst, int row, int c,
                                            const float acc[8], float id) {
    float q = id * id;
    __half2 p0 = __floats2half2_rn(acc[0] * q, acc[1] * q);
    __half2 p1 = __floats2half2_rn(acc[2] * q, acc[3] * q);
    __half2 p2 = __floats2half2_rn(acc[4] * q, acc[5] * q);
    __half2 p3 = __floats2half2_rn(acc[6] * q, acc[7] * q);
    uint4 o;
    o.x = *reinterpret_cast<unsigned*>(&p0);
    o.y = *reinterpret_cast<unsigned*>(&p1);
    o.z = *reinterpret_cast<unsigned*>(&p2);
    o.w = *reinterpret_cast<unsigned*>(&p3);
    reinterpret_cast<uint4*>(dst)[(size_t)row * 8 + c] = o;
}

__device__ __forceinline__ void rmw_out(float* out, int row, int c,
                                        const float acc[8], float id) {
    float s = 0.25f * id;
    float4* op = reinterpret_cast<float4*>(out + (size_t)row * DIM + c * 8);
    float4 t0 = op[0], t1 = op[1];
    t0.x += s * acc[0]; t0.y += s * acc[1];
    t0.z += s * acc[2]; t0.w += s * acc[3];
    t1.x += s * acc[4]; t1.y += s * acc[5];
    t1.z += s * acc[6]; t1.w += s * acc[7];
    op[0] = t0; op[1] = t1;
}

// One warp = rows (w, w+6000). Lane l: group g=l>>3 serves neighbor slot k+g /
// k+4+g of each row; chunk c=l&7 owns dims [8c,8c+8). 4 independent LDG.128
// per iteration (16 outstanding per warp across the 2 unrolled rows).
// Padded slots gather the permanent zero row NN.
template <int SRC, int DST, bool LAST>
__global__ void __launch_bounds__(256, 4)
spmm_kernel(float* __restrict__ out) {
    const int w    = (blockIdx.x * 256 + threadIdx.x) >> 5;  // 0..5999
    const int lane = threadIdx.x & 31;
    const int g    = lane >> 3;
    const int c    = lane & 7;
    if (w >= HALFN) return;

    const int rA = w, rB = w + HALFN;
    const uint4* __restrict__ y   = reinterpret_cast<const uint4*>(g_y[SRC]);
    const int*   __restrict__ nbA = g_nbr + (size_t)rA * PAD;
    const int*   __restrict__ nbB = g_nbr + (size_t)rB * PAD;
    const int dA = g_deg2[rA];
    const int dB = g_deg2[rB];
    const int dmax = dA > dB ? dA : dB;

    float accA[8] = {0.f, 0.f, 0.f, 0.f, 0.f, 0.f, 0.f, 0.f};
    float accB[8] = {0.f, 0.f, 0.f, 0.f, 0.f, 0.f, 0.f, 0.f};

    for (int k = 0; k < dmax; k += 8) {
        int k0 = k + g, k1 = k + 4 + g;
        int jA0 = (k0 < dA) ? __ldg(nbA + k0) : NN;
        int jA1 = (k1 < dA) ? __ldg(nbA + k1) : NN;
        int jB0 = (k0 < dB) ? __ldg(nbB + k0) : NN;
        int jB1 = (k1 < dB) ? __ldg(nbB + k1) : NN;
        uint4 vA0 = __ldg(y + (size_t)jA0 * 8 + c);
        uint4 vA1 = __ldg(y + (size_t)jA1 * 8 + c);
        uint4 vB0 = __ldg(y + (size_t)jB0 * 8 + c);
        uint4 vB1 = __ldg(y + (size_t)jB1 * 8 + c);
        acc8(accA, vA0);
        acc8(accA, vA1);
        acc8(accB, vB0);
        acc8(accB, vB1);
    }

    reduce_groups(accA);
    reduce_groups(accB);

    const float idA = g_invd[rA];
    const float idB = g_invd[rB];

    // Epilogue spread across lane-groups: g0/g1 -> row A, g2/g3 -> row B.
    if (!LAST) {
        if (g == 0) store_ynext(g_y[DST], rA, c, accA, idA);
        if (g == 2) store_ynext(g_y[DST], rB, c, accB, idB);
    }
    if (g == 1) rmw_out(out, rA, c, accA, idA);
    if (g == 3) rmw_out(out, rB, c, accB, idB);

    if (LAST) {  // fold bitmap cleanup: clear exactly the touched words
        for (int k = lane; k < dA; k += 32)
            g_bitmap[(size_t)rA * WPR + (nbA[k] >> 5)] = 0u;
        for (int k = lane; k < dB; k += 32)
            g_bitmap[(size_t)rB * WPR + (nbB[k] >> 5)] = 0u;
    }
}

// ---------------------------------------------------------------------------
extern "C" void kernel_launch(void* const* d_in, const int* in_sizes, int n_in,
                              void* d_out, int out_size) {
    const int*   edge = (const int*)d_in[0];   // (2, E) int32
    const float* ue   = (const float*)d_in[1]; // (8000, 64) f32
    const float* ie   = (const float*)d_in[2]; // (4000, 64) f32
    float*       out  = (float*)d_out;         // (12000, 64) f32

    int E = in_sizes[0] / 2;

    build_kernel<<<(E + 255) / 256, 256>>>(edge, E);
    init_kernel<<<(NN * DIM / 4 + 255) / 256, 256>>>(ue, ie, out);

    const int SPMM_BLOCKS = (HALFN * 32) / 256;      // 750 blocks, warp per pair
    spmm_kernel<0, 1, false><<<SPMM_BLOCKS, 256>>>(out);
    spmm_kernel<1, 2, false><<<SPMM_BLOCKS, 256>>>(out);
    spmm_kernel<2, 0, true ><<<SPMM_BLOCKS, 256>>>(out);
}

// round 10
// speedup vs baseline: 1.1970x; 1.0443x over previous
#include <cuda_runtime.h>
#include <cuda_fp16.h>

// LightGCN: final = 0.25 * (I + A^ + A^2 + A^3) emb, A^ = D^-1/2 A D^-1/2
// N = 12000 (8000 users + 4000 items), dim 64, 300k undirected edges.
//
// R9: no out RMW — last pass composes out = 0.25(e + sqrt(d)(y1+y2) + s3/sqrt(d))
// from row-local data. Index loads software-pipelined one iteration ahead.
// HADD2 pair-accumulation halves convert/add count. Two rows per warp (R8).

#define NUSERS 8000
#define NITEMS 4000
#define NN     12000
#define HALFN  6000
#define DIM    64
#define WPR    375           // bitmap words per row: ceil(12000/32)
#define PAD    128           // ELL row pad (mean deg ~50, P(>128) ~ 1e-20)

// Scratch (device globals: zero-init at load; left clean after every call).
__device__ unsigned g_bitmap[(size_t)NN * WPR];       // 18 MB dedup bitmap
__device__ int      g_nbr[(size_t)NN * PAD];          // 6 MB ELL column indices
__device__ int      g_deg[NN];                        // build counter (reset each call)
__device__ int      g_deg2[NN];                       // snapshot for spmm
__device__ float    g_invd[NN];
__device__ __half   g_y[3][(size_t)(NN + 1) * DIM];   // +1: row NN is permanent zeros

// ---------------------------------------------------------------------------
// Dedup via bitmap atomicOr (old value elects exactly one winner per distinct
// directed edge); winner appends to ELL. Self-loops counted once (matches ref).
__device__ __forceinline__ void add_edge(int a, int b) {
    unsigned bit = 1u << (b & 31);
    unsigned old = atomicOr(&g_bitmap[(size_t)a * WPR + (b >> 5)], bit);
    if (!(old & bit)) {
        int pos = atomicAdd(&g_deg[a], 1);
        g_nbr[(size_t)a * PAD + pos] = b;
    }
}

__global__ void build_kernel(const int* __restrict__ ei, int E) {
    int e = blockIdx.x * blockDim.x + threadIdx.x;
    if (e >= E) return;
    int u = ei[e];
    int v = ei[E + e];
    add_edge(u, v);
    add_edge(v, u);
}

// ---------------------------------------------------------------------------
// y0 = half(emb * d^-1/2) only (out is written solely by the last spmm pass).
// invd inline; one thread per row snapshots & resets deg.
__global__ void init_kernel(const float* __restrict__ ue,
                            const float* __restrict__ ie) {
    int i = blockIdx.x * blockDim.x + threadIdx.x;   // float4 index
    if (i >= NN * DIM / 4) return;
    int n = i >> 4;                                  // 16 float4 per row
    int d = g_deg[n];
    float id = rsqrtf((float)(d < 1 ? 1 : d));
    if ((i & 15) == 0) {
        g_deg2[n] = d;
        g_deg[n]  = 0;                               // clean for next call
        g_invd[n] = id;
    }
    float4 e = (n < NUSERS)
        ? reinterpret_cast<const float4*>(ue)[i]
        : reinterpret_cast<const float4*>(ie)[i - NUSERS * (DIM / 4)];
    __half2* yp = reinterpret_cast<__half2*>(g_y[0]) + (size_t)i * 2;
    yp[0] = __floats2half2_rn(e.x * id, e.y * id);
    yp[1] = __floats2half2_rn(e.z * id, e.w * id);
}

// ---------------------------------------------------------------------------
// Pair-sum two gathered 8-half chunks in fp16 (HADD2 x4), then convert & add
// into the fp32 accumulator (one extra fp16 rounding; negligible vs 1e-3 gate).
__device__ __forceinline__ void acc8_pair(float acc[8], uint4 a, uint4 b) {
    __half2 h0 = __hadd2(*reinterpret_cast<__half2*>(&a.x),
                         *reinterpret_cast<__half2*>(&b.x));
    __half2 h1 = __hadd2(*reinterpret_cast<__half2*>(&a.y),
                         *reinterpret_cast<__half2*>(&b.y));
    __half2 h2 = __hadd2(*reinterpret_cast<__half2*>(&a.z),
                         *reinterpret_cast<__half2*>(&b.z));
    __half2 h3 = __hadd2(*reinterpret_cast<__half2*>(&a.w),
                         *reinterpret_cast<__half2*>(&b.w));
    float2 f0 = __half22float2(h0), f1 = __half22float2(h1);
    float2 f2 = __half22float2(h2), f3 = __half22float2(h3);
    acc[0] += f0.x; acc[1] += f0.y; acc[2] += f1.x; acc[3] += f1.y;
    acc[4] += f2.x; acc[5] += f2.y; acc[6] += f3.x; acc[7] += f3.y;
}

__device__ __forceinline__ void reduce_groups(float acc[8]) {
    #pragma unroll
    for (int i = 0; i < 8; ++i) {
        acc[i] += __shfl_xor_sync(0xffffffffu, acc[i], 8);
        acc[i] += __shfl_xor_sync(0xffffffffu, acc[i], 16);
    }
}

__device__ __forceinline__ void store_ynext(__half* dst, int row, int c,
                                            const float acc[8], float id) {
    float q = id * id;
    __half2 p0 = __floats2half2_rn(acc[0] * q, acc[1] * q);
    __half2 p1 = __floats2half2_rn(acc[2] * q, acc[3] * q);
    __half2 p2 = __floats2half2_rn(acc[4] * q, acc[5] * q);
    __half2 p3 = __floats2half2_rn(acc[6] * q, acc[7] * q);
    uint4 o;
    o.x = *reinterpret_cast<unsigned*>(&p0);
    o.y = *reinterpret_cast<unsigned*>(&p1);
    o.z = *reinterpret_cast<unsigned*>(&p2);
    o.w = *reinterpret_cast<unsigned*>(&p3);
    reinterpret_cast<uint4*>(dst)[(size_t)row * 8 + c] = o;
}

// Final composition for one row's 8-dim chunk c (8 lanes of one group):
// out = 0.25 * (e + sqrt(d)*(y1+y2) + invd*s3). Fully writes out (no RMW).
__device__ __forceinline__ void compose_out(float* __restrict__ out,
                                            const float* __restrict__ ue,
                                            const float* __restrict__ ie,
                                            int row, int c,
                                            const float acc[8],
                                            float id, float sd) {
    const float* e = (row < NUSERS) ? ue + (size_t)row * DIM
                                    : ie + (size_t)(row - NUSERS) * DIM;
    uint4 w1 = reinterpret_cast<const uint4*>(g_y[1])[(size_t)row * 8 + c];
    uint4 w2 = reinterpret_cast<const uint4*>(g_y[2])[(size_t)row * 8 + c];
    float4 e0 = reinterpret_cast<const float4*>(e + c * 8)[0];
    float4 e1 = reinterpret_cast<const float4*>(e + c * 8)[1];

    __half2 s0 = __hadd2(*reinterpret_cast<__half2*>(&w1.x),
                         *reinterpret_cast<__half2*>(&w2.x));
    __half2 s1 = __hadd2(*reinterpret_cast<__half2*>(&w1.y),
                         *reinterpret_cast<__half2*>(&w2.y));
    __half2 s2 = __hadd2(*reinterpret_cast<__half2*>(&w1.z),
                         *reinterpret_cast<__half2*>(&w2.z));
    __half2 s3h = __hadd2(*reinterpret_cast<__half2*>(&w1.w),
                          *reinterpret_cast<__half2*>(&w2.w));
    float2 y0 = __half22float2(s0), y1 = __half22float2(s1);
    float2 y2 = __half22float2(s2), y3 = __half22float2(s3h);

    float4 o0, o1;
    o0.x = 0.25f * (e0.x + sd * y0.x + id * acc[0]);
    o0.y = 0.25f * (e0.y + sd * y0.y + id * acc[1]);
    o0.z = 0.25f * (e0.z + sd * y1.x + id * acc[2]);
    o0.w = 0.25f * (e0.w + sd * y1.y + id * acc[3]);
    o1.x = 0.25f * (e1.x + sd * y2.x + id * acc[4]);
    o1.y = 0.25f * (e1.y + sd * y2.y + id * acc[5]);
    o1.z = 0.25f * (e1.z + sd * y3.x + id * acc[6]);
    o1.w = 0.25f * (e1.w + sd * y3.y + id * acc[7]);
    float4* op = reinterpret_cast<float4*>(out + (size_t)row * DIM + c * 8);
    op[0] = o0;
    op[1] = o1;
}

// One warp = rows (w, w+6000). Lane l: group g=l>>3 serves neighbor slots
// k+g / k+4+g of each row; chunk c=l&7 owns dims [8c,8c+8). Index loads are
// software-pipelined one iteration ahead so gathers never wait on them.
// Padded slots gather the permanent zero row NN.
template <int SRC, int DST, bool LAST>
__global__ void __launch_bounds__(256, 4)
spmm_kernel(float* __restrict__ out,
            const float* __restrict__ ue, const float* __restrict__ ie) {
    const int w    = (blockIdx.x * 256 + threadIdx.x) >> 5;  // 0..5999
    const int lane = threadIdx.x & 31;
    const int g    = lane >> 3;
    const int c    = lane & 7;
    if (w >= HALFN) return;

    const int rA = w, rB = w + HALFN;
    const uint4* __restrict__ y   = reinterpret_cast<const uint4*>(g_y[SRC]);
    const int*   __restrict__ nbA = g_nbr + (size_t)rA * PAD;
    const int*   __restrict__ nbB = g_nbr + (size_t)rB * PAD;
    const int dA = g_deg2[rA];
    const int dB = g_deg2[rB];
    const int dmax = dA > dB ? dA : dB;

    float accA[8] = {0.f, 0.f, 0.f, 0.f, 0.f, 0.f, 0.f, 0.f};
    float accB[8] = {0.f, 0.f, 0.f, 0.f, 0.f, 0.f, 0.f, 0.f};

    // Pipelined indices for the current iteration.
    int k0 = g, k1 = 4 + g;
    int jA0 = (k0 < dA) ? __ldg(nbA + k0) : NN;
    int jA1 = (k1 < dA) ? __ldg(nbA + k1) : NN;
    int jB0 = (k0 < dB) ? __ldg(nbB + k0) : NN;
    int jB1 = (k1 < dB) ? __ldg(nbB + k1) : NN;

    for (int k = 0; k < dmax; k += 8) {
        // Prefetch next iteration's indices (independent of this iter's gathers).
        int n0 = k + 8 + g, n1 = k + 12 + g;
        int tA0 = (n0 < dA) ? __ldg(nbA + n0) : NN;
        int tA1 = (n1 < dA) ? __ldg(nbA + n1) : NN;
        int tB0 = (n0 < dB) ? __ldg(nbB + n0) : NN;
        int tB1 = (n1 < dB) ? __ldg(nbB + n1) : NN;

        uint4 vA0 = __ldg(y + (size_t)jA0 * 8 + c);
        uint4 vA1 = __ldg(y + (size_t)jA1 * 8 + c);
        uint4 vB0 = __ldg(y + (size_t)jB0 * 8 + c);
        uint4 vB1 = __ldg(y + (size_t)jB1 * 8 + c);
        acc8_pair(accA, vA0, vA1);
        acc8_pair(accB, vB0, vB1);

        jA0 = tA0; jA1 = tA1; jB0 = tB0; jB1 = tB1;
    }

    reduce_groups(accA);
    reduce_groups(accB);

    const float idA = g_invd[rA];
    const float idB = g_invd[rB];

    if (!LAST) {
        // Passes 1-2: store only y_next (no out traffic at all).
        if (g == 0) store_ynext(g_y[DST], rA, c, accA, idA);
        if (g == 2) store_ynext(g_y[DST], rB, c, accB, idB);
    } else {
        // Last pass: compose out once from row-local data.
        float sdA = sqrtf((float)(dA < 1 ? 1 : dA));
        float sdB = sqrtf((float)(dB < 1 ? 1 : dB));
        if (g == 1) compose_out(out, ue, ie, rA, c, accA, idA, sdA);
        if (g == 3) compose_out(out, ue, ie, rB, c, accB, idB, sdB);
        // Fold bitmap cleanup: clear exactly the touched words.
        for (int k = lane; k < dA; k += 32)
            g_bitmap[(size_t)rA * WPR + (nbA[k] >> 5)] = 0u;
        for (int k = lane; k < dB; k += 32)
            g_bitmap[(size_t)rB * WPR + (nbB[k] >> 5)] = 0u;
    }
}

// ---------------------------------------------------------------------------
extern "C" void kernel_launch(void* const* d_in, const int* in_sizes, int n_in,
                              void* d_out, int out_size) {
    const int*   edge = (const int*)d_in[0];   // (2, E) int32
    const float* ue   = (const float*)d_in[1]; // (8000, 64) f32
    const float* ie   = (const float*)d_in[2]; // (4000, 64) f32
    float*       out  = (float*)d_out;         // (12000, 64) f32

    int E = in_sizes[0] / 2;

    build_kernel<<<(E + 255) / 256, 256>>>(edge, E);
    init_kernel<<<(NN * DIM / 4 + 255) / 256, 256>>>(ue, ie);

    const int SPMM_BLOCKS = (HALFN * 32) / 256;      // 750 blocks, warp per pair
    spmm_kernel<0, 1, false><<<SPMM_BLOCKS, 256>>>(out, ue, ie);
    spmm_kernel<1, 2, false><<<SPMM_BLOCKS, 256>>>(out, ue, ie);
    spmm_kernel<2, 0, true ><<<SPMM_BLOCKS, 256>>>(out, ue, ie);
}